// round 10
// baseline (speedup 1.0000x reference)
#include <cuda_runtime.h>
#include <cuda_fp16.h>
#include <math_constants.h>
#include <cstdint>

// Problem constants: B=512, D=256, C=100000, m=4, lambda=1000
#define MAX_C 100000
#define MAX_B 512
#define DD    256

__device__ __half g_wh[(size_t)MAX_C * DD];   // fp16(normalized W)
__device__ __half g_xh[(size_t)MAX_B * DD];   // fp16(normalized X)
__device__ float  g_xlen[MAX_B];

// ---------------------------------------------------------------------------
// Helpers
// ---------------------------------------------------------------------------
__device__ __forceinline__ uint32_t smem_u32(const void* p) {
    uint32_t a;
    asm("{ .reg .u64 t; cvta.to.shared.u64 t, %1; cvt.u32.u64 %0, t; }" : "=r"(a) : "l"(p));
    return a;
}
__device__ __forceinline__ void cp_async16(uint32_t dst, const void* src) {
    asm volatile("cp.async.cg.shared.global [%0], [%1], 16;" :: "r"(dst), "l"(src));
}
__device__ __forceinline__ void cp_commit() {
    asm volatile("cp.async.commit_group;" ::: "memory");
}
template <int N> __device__ __forceinline__ void cp_wait() {
    asm volatile("cp.async.wait_group %0;" :: "n"(N) : "memory");
}
__device__ __forceinline__ void ldsm_x4(uint32_t& r0, uint32_t& r1, uint32_t& r2, uint32_t& r3,
                                        uint32_t addr) {
    asm volatile("ldmatrix.sync.aligned.m8n8.x4.shared.b16 {%0,%1,%2,%3}, [%4];"
                 : "=r"(r0), "=r"(r1), "=r"(r2), "=r"(r3) : "r"(addr));
}
__device__ __forceinline__ void mma_16816(float& c0, float& c1, float& c2, float& c3,
                                          uint32_t a0, uint32_t a1, uint32_t a2, uint32_t a3,
                                          uint32_t b0, uint32_t b1) {
    asm volatile("mma.sync.aligned.m16n8k16.row.col.f32.f16.f16.f32 "
                 "{%0,%1,%2,%3}, {%4,%5,%6,%7}, {%8,%9}, {%0,%1,%2,%3};"
                 : "+f"(c0), "+f"(c1), "+f"(c2), "+f"(c3)
                 : "r"(a0), "r"(a1), "r"(a2), "r"(a3), "r"(b0), "r"(b1));
}

// ---------------------------------------------------------------------------
// Merged prep: rows [0,C) -> normalize W row; rows [C,C+B) -> normalize X row.
// ---------------------------------------------------------------------------
__global__ void prep_kernel(const float* __restrict__ W, const float* __restrict__ X,
                            int C, int B) {
    int row  = (blockIdx.x * blockDim.x + threadIdx.x) >> 5;
    int lane = threadIdx.x & 31;
    if (row >= C + B) return;
    const bool isx = row >= C;
    const int  r   = isx ? row - C : row;
    const float* src = (isx ? X : W) + (size_t)r * DD;
    __half*      dst = (isx ? g_xh : g_wh) + (size_t)r * DD;

    float4 v0 = *(const float4*)(src + lane * 4);
    float4 v1 = *(const float4*)(src + 128 + lane * 4);
    float s = v0.x*v0.x + v0.y*v0.y + v0.z*v0.z + v0.w*v0.w
            + v1.x*v1.x + v1.y*v1.y + v1.z*v1.z + v1.w*v1.w;
    #pragma unroll
    for (int o = 16; o; o >>= 1) s += __shfl_xor_sync(0xffffffffu, s, o);
    float inv = rsqrtf(s);
    if (isx && lane == 0) g_xlen[r] = s * inv;   // len
    __half2 h0 = __floats2half2_rn(v0.x * inv, v0.y * inv);
    __half2 h1 = __floats2half2_rn(v0.z * inv, v0.w * inv);
    __half2 h2 = __floats2half2_rn(v1.x * inv, v1.y * inv);
    __half2 h3 = __floats2half2_rn(v1.z * inv, v1.w * inv);
    *(__half2*)(dst + lane * 4)           = h0;
    *(__half2*)(dst + lane * 4 + 2)       = h1;
    *(__half2*)(dst + 128 + lane * 4)     = h2;
    *(__half2*)(dst + 128 + lane * 4 + 2) = h3;
}

// ---------------------------------------------------------------------------
// Persistent GEMM: 296 CTAs (2/SM). CTA = (m-tile bid&3, slot bid>>2).
// Slot walks n-tiles slot, slot+NSLOT, ... ; B pipeline continuous across
// tiles (ring of 3, prefetch distance 2). A K-resident, loaded once.
// ---------------------------------------------------------------------------
#define BM 128
#define BN 128
#define BK 64
#define NCHUNK 4
#define NSLOT  74
#define NCTA   296

#define A_OFF      0                     // 4 slabs of 16 KB = 65536
#define B_OFF      65536                 // ring 3 x 16 KB = 49152
#define SMEM_TOTAL 114688                // 112 KB -> 2 CTAs/SM

__global__ __launch_bounds__(256, 2)
void angle_mma_kernel(const int* __restrict__ Y, float* __restrict__ out,
                      int C, int ntiles)
{
    extern __shared__ char smem[];
    const uint32_t sbase = smem_u32(smem);
    const int tid  = threadIdx.x;
    const int wid  = tid >> 5;
    const int lane = tid & 31;
    const int wm   = wid >> 2;     // 0..1 : warp m (64 rows)
    const int wn   = wid & 3;      // 0..3 : warp n (32 cols)

    const int bm   = (blockIdx.x & 3) * BM;
    const int slot = blockIdx.x >> 2;

    // number of tiles for this slot
    const int J = (ntiles - slot + NSLOT - 1) / NSLOT;
    if (J <= 0) return;
    const int QMAX = J * NCHUNK;

    // ---- loaders ----
    auto load_a_all = [&]() {       // 128 rows x 256 k, 4 slabs of 16 KB
        for (int i = 0; i < 16; i++) {
            int t2 = tid + i * 256;
            int chunk = t2 >> 10;
            int w3    = t2 & 1023;
            int row = w3 >> 3, blk = w3 & 7;
            uint32_t off = (uint32_t)(row * 128) + (uint32_t)(((blk ^ (row & 7)) << 4));
            cp_async16(sbase + A_OFF + chunk * 16384 + off,
                       g_xh + (size_t)(bm + row) * DD + chunk * BK + blk * 8);
        }
    };
    auto issue_chunk = [&](int q) {            // B chunk q (global counter)
        const int j  = q >> 2;
        const int ck = q & 3;
        const int bn = (slot + j * NSLOT) * BN;
        const uint32_t bb = sbase + B_OFF + (uint32_t)(q % 3) * 16384;
        #pragma unroll
        for (int i = 0; i < 4; i++) {
            int g = tid + i * 256;
            int row = g >> 3, blk = g & 7;
            int rg = bn + row; if (rg >= C) rg = C - 1;
            uint32_t off = (uint32_t)(row * 128) + (uint32_t)(((blk ^ (row & 7)) << 4));
            cp_async16(bb + off, g_wh + (size_t)rg * DD + ck * BK + blk * 8);
        }
        cp_commit();
    };

    // ---- prologue ----
    load_a_all();
    issue_chunk(0);                 // commits A + B0 together
    if (QMAX > 1) issue_chunk(1);

    // per-lane fragment row bases, XOR-composable: rel = row*128 + ((row&7)<<4)
    const int a_hi = lane >> 4;
    uint32_t a_rel[4], b_rel[2];
    #pragma unroll
    for (int mt = 0; mt < 4; mt++) {
        int r = wm * 64 + mt * 16 + (lane & 15);
        a_rel[mt] = (uint32_t)(r * 128) + (uint32_t)((r & 7) << 4);
    }
    #pragma unroll
    for (int bt = 0; bt < 2; bt++) {
        int r = wn * 32 + bt * 16 + ((lane >> 3) & 1) * 8 + (lane & 7);
        b_rel[bt] = (uint32_t)(r * 128) + (uint32_t)((r & 7) << 4);
    }

    const float inv_pi     = 1.0f / CUDART_PI_F;
    const float inv_1plamb = 1.0f / 1001.0f;

    // ---- persistent tile loop ----
    for (int j = 0; j < J; j++) {
        float c[4][4][4];
        #pragma unroll
        for (int mt = 0; mt < 4; mt++)
            #pragma unroll
            for (int nt = 0; nt < 4; nt++)
                #pragma unroll
                for (int q = 0; q < 4; q++) c[mt][nt][q] = 0.f;

        #pragma unroll
        for (int ck = 0; ck < NCHUNK; ck++) {
            const int q = j * NCHUNK + ck;
            if (q == QMAX - 1) cp_wait<0>(); else cp_wait<1>();
            __syncthreads();                      // B[q%3] visible; old readers done

            if (q + 2 < QMAX) issue_chunk(q + 2); // refill idle ring slot

            const uint32_t ab = sbase + A_OFF + (uint32_t)ck * 16384;
            const uint32_t bb = sbase + B_OFF + (uint32_t)(q % 3) * 16384;

            uint32_t a[2][4][4], b[2][2][4];
            const uint32_t k0 = (uint32_t)(a_hi << 4);
            #pragma unroll
            for (int mt = 0; mt < 4; mt++)
                ldsm_x4(a[0][mt][0], a[0][mt][1], a[0][mt][2], a[0][mt][3],
                        ab + (a_rel[mt] ^ k0));
            #pragma unroll
            for (int bt = 0; bt < 2; bt++)
                ldsm_x4(b[0][bt][0], b[0][bt][1], b[0][bt][2], b[0][bt][3],
                        bb + (b_rel[bt] ^ k0));

            #pragma unroll
            for (int ks = 0; ks < 4; ks++) {
                const int cur = ks & 1, nxt = cur ^ 1;
                if (ks < 3) {
                    const uint32_t kc = (uint32_t)(((ks + 1) * 2 + a_hi) << 4);
                    #pragma unroll
                    for (int mt = 0; mt < 4; mt++)
                        ldsm_x4(a[nxt][mt][0], a[nxt][mt][1], a[nxt][mt][2], a[nxt][mt][3],
                                ab + (a_rel[mt] ^ kc));
                    #pragma unroll
                    for (int bt = 0; bt < 2; bt++)
                        ldsm_x4(b[nxt][bt][0], b[nxt][bt][1], b[nxt][bt][2], b[nxt][bt][3],
                                bb + (b_rel[bt] ^ kc));
                }
                #pragma unroll
                for (int mt = 0; mt < 4; mt++) {
                    #pragma unroll
                    for (int nt = 0; nt < 4; nt++) {
                        const int bt = nt >> 1, sub = nt & 1;
                        mma_16816(c[mt][nt][0], c[mt][nt][1], c[mt][nt][2], c[mt][nt][3],
                                  a[cur][mt][0], a[cur][mt][1], a[cur][mt][2], a[cur][mt][3],
                                  b[cur][bt][sub], b[cur][bt][2 + sub]);
                    }
                }
            }
        }

        // ---- epilogue for tile j (next tile's B loads already in flight) ----
        const int bn = (slot + j * NSLOT) * BN;
        #pragma unroll
        for (int mt = 0; mt < 4; mt++) {
            const int r0 = bm + wm * 64 + mt * 16 + (lane >> 2);
            const int r1 = r0 + 8;
            const float xl0 = g_xlen[r0], xl1 = g_xlen[r1];
            const int  lab0 = Y[r0],      lab1 = Y[r1];
            #pragma unroll
            for (int nt = 0; nt < 4; nt++) {
                const int col = bn + wn * 32 + nt * 8 + (lane & 3) * 2;
                if (col >= C) continue;          // col even, C even
                #pragma unroll
                for (int half = 0; half < 2; half++) {
                    const int   rr  = half ? r1 : r0;
                    const float xl  = half ? xl1 : xl0;
                    const int   lab = half ? lab1 : lab0;
                    float v0 = c[mt][nt][half * 2 + 0];
                    float v1 = c[mt][nt][half * 2 + 1];
                    v0 = fminf(fmaxf(v0, -1.0f), 1.0f);
                    v1 = fminf(fmaxf(v1, -1.0f), 1.0f);
                    float f0 = v0 * xl, f1 = v1 * xl;
                    if (col == lab || col + 1 == lab) {
                        const bool second = (col + 1 == lab);
                        float cv = second ? v1 : v0;
                        float c2   = cv * cv;
                        float cosm = 8.0f * c2 * c2 - 8.0f * c2 + 1.0f;
                        float kf   = floorf(4.0f * acosf(cv) * inv_pi);
                        float sign = 1.0f - 2.0f * fmodf(kf, 2.0f);
                        float phi  = sign * cosm - 2.0f * kf;
                        float fm   = second ? f1 : f0;
                        fm += (phi * xl - fm) * inv_1plamb;
                        if (second) f1 = fm; else f0 = fm;
                    }
                    *(float2*)(out + (size_t)rr * C + col) = make_float2(f0, f1);
                }
            }
        }
    }
}

// ---------------------------------------------------------------------------
// Launch
// ---------------------------------------------------------------------------
extern "C" void kernel_launch(void* const* d_in, const int* in_sizes, int n_in,
                              void* d_out, int out_size)
{
    const float* x = (const float*)d_in[0];
    const float* w = (const float*)d_in[1];
    const int*   y = (const int*)d_in[2];
    float* out     = (float*)d_out;

    const int B = in_sizes[2];            // 512
    const int D = in_sizes[0] / B;        // 256
    const int C = in_sizes[1] / D;        // 100000
    (void)D;

    static bool attr_set = false;
    if (!attr_set) {
        cudaFuncSetAttribute(angle_mma_kernel,
                             cudaFuncAttributeMaxDynamicSharedMemorySize, SMEM_TOTAL);
        attr_set = true;
    }

    {
        int wpb = 8;
        int rows = C + B;
        prep_kernel<<<(rows + wpb - 1) / wpb, wpb * 32>>>(w, x, C, B);
    }

    const int ntiles = (C + BN - 1) / BN;          // 782
    angle_mma_kernel<<<NCTA, 256, SMEM_TOTAL>>>(y, out, C, ntiles);
}